// round 15
// baseline (speedup 1.0000x reference)
#include <cuda_runtime.h>
#include <cuda_fp16.h>
#include <math.h>
#include <stdint.h>

#define B 256
#define T 512
#define F 128
#define H 256
#define H3 768
#define BH (B * H)

// ---------------------------------------------------------------------------
// Helpers
// ---------------------------------------------------------------------------
__device__ __forceinline__ float tanh_fast(float x) {
    float y;
    asm("tanh.approx.f32 %0, %1;" : "=f"(y) : "f"(x));
    return y;
}
__device__ __forceinline__ float sig_fast(float x) {
    return fmaf(0.5f, tanh_fast(0.5f * x), 0.5f);
}
__device__ __forceinline__ uint32_t pack_h2(float lo, float hi) {
    half2 h = __floats2half2_rn(lo, hi);
    return *reinterpret_cast<uint32_t*>(&h);
}
__device__ __forceinline__ uint32_t smem_u32(const void* p) {
    uint32_t a;
    asm("{ .reg .u64 t; cvta.to.shared.u64 t, %1; cvt.u32.u64 %0, t; }"
        : "=r"(a) : "l"(p));
    return a;
}
__device__ __forceinline__ void mma_f16(float* d,
                                        uint32_t a0, uint32_t a1, uint32_t a2, uint32_t a3,
                                        uint32_t b0, uint32_t b1) {
    asm volatile(
        "mma.sync.aligned.m16n8k16.row.col.f32.f16.f16.f32 "
        "{%0,%1,%2,%3}, {%4,%5,%6,%7}, {%8,%9}, {%0,%1,%2,%3};"
        : "+f"(d[0]), "+f"(d[1]), "+f"(d[2]), "+f"(d[3])
        : "r"(a0), "r"(a1), "r"(a2), "r"(a3), "r"(b0), "r"(b1));
}
__device__ __forceinline__ void ldsm_x4(uint32_t& a0, uint32_t& a1,
                                        uint32_t& a2, uint32_t& a3, uint32_t saddr) {
    asm volatile("ldmatrix.sync.aligned.m8n8.x4.shared.b16 {%0,%1,%2,%3}, [%4];"
                 : "=r"(a0), "=r"(a1), "=r"(a2), "=r"(a3) : "r"(saddr));
}
__device__ __forceinline__ uint32_t mapa_u32(uint32_t addr, int rank) {
    uint32_t r;
    asm("mapa.shared::cluster.u32 %0, %1, %2;" : "=r"(r) : "r"(addr), "r"(rank));
    return r;
}
__device__ __forceinline__ void st_cluster_u16(uint32_t addr, uint16_t v) {
    asm volatile("st.shared::cluster.u16 [%0], %1;" :: "r"(addr), "h"(v) : "memory");
}
__device__ __forceinline__ void mbar_arrive_rel_cluster(uint32_t addr) {
    asm volatile("mbarrier.arrive.release.cluster.shared::cluster.b64 _, [%0];"
                 :: "r"(addr) : "memory");
}
__device__ __forceinline__ void mbar_wait_parity_acq_cluster(uint32_t addr,
                                                             uint32_t parity) {
    asm volatile(
        "{\n\t"
        ".reg .pred p;\n\t"
        "WAITLOOP_%=:\n\t"
        "mbarrier.try_wait.parity.acquire.cluster.shared::cta.b64 p, [%0], %1;\n\t"
        "@!p bra WAITLOOP_%=;\n\t"
        "}"
        :: "r"(addr), "r"(parity) : "memory");
}
#define CLUSTER_SYNC() do { \
    asm volatile("barrier.cluster.arrive.aligned;" ::: "memory"); \
    asm volatile("barrier.cluster.wait.aligned;" ::: "memory"); \
} while (0)

// ---------------------------------------------------------------------------
// Persistent fused GRU kernel — cluster/DSMEM-push version.
// Grid (8 j-tiles, 16 b-groups) = 128 blocks, cluster (8,1,1), 512 thr.
//
// Warps 0-11:  recurrence mh = h(t-1) @ Wr; one n8-chunk each (16 HMMA);
//              Wr frags in 32 regs; A frags via ldmatrix.x4.
//              h arrives by mbarrier wait (acquire.cluster), NOT L2.
// Warps 12-15: input projection mx_{t+1} (one step ahead), mxs dbl-buf.
// Phase C:     512 threads, 1 element each; fp32 gates; PUSH own fp16 h
//              element into all 8 cluster CTAs' hsh (st.shared::cluster)
//              + 8 remote mbarrier arrives (release.cluster). out STG after.
// NO barrier.cluster in the loop; one at init and exit only.
// ---------------------------------------------------------------------------
#define BT 16
#define JT 32
#define HST 264                     // hs row stride in halves (LDSM-clean)
#define XST 136                     // xs row stride in halves
#define PTS 100                     // mh tile row stride (f32)
#define MXS 100                     // mx tile row stride (f32)

#define HSBUF_HALVES (BT * HST)            // one h buffer
#define HSBUF_BYTES (HSBUF_HALVES * 2)     // 8448
#define HS_BYTES (2 * HSBUF_BYTES)         // 16896 (double-buffered)
#define XS_BYTES (BT * XST * 2)            // 4352
#define PT_BYTES (BT * PTS * 4)            // 6400
#define MX_BYTES (2 * BT * MXS * 4)        // 12800
#define MB_OFF (HS_BYTES + XS_BYTES + PT_BYTES + MX_BYTES)
#define SMEM_BYTES (MB_OFF + 16)

extern __shared__ char smem_dyn[];

__global__ __launch_bounds__(512, 1) __cluster_dims__(8, 1, 1)
void gru_persist(const float* __restrict__ x,
                 const float* __restrict__ wk,
                 const float* __restrict__ wr,
                 const float* __restrict__ bias,
                 float* __restrict__ out) {
    half*  hsh = (half*)(smem_dyn);                         // [2][16][HST]
    half*  xsh = (half*)(smem_dyn + HS_BYTES);              // [16][XST]
    float* pt  = (float*)(smem_dyn + HS_BYTES + XS_BYTES);  // [16][PTS]
    float* mxs = (float*)(smem_dyn + HS_BYTES + XS_BYTES + PT_BYTES); // [2][16][MXS]

    const int tid = (int)threadIdx.x;              // 0..511
    const int wid = tid >> 5;                      // 0..15
    const int lane = tid & 31;
    const int jb = (int)blockIdx.x;                // 0..7 == cluster rank
    const int ib = (int)blockIdx.y;                // 0..15
    const int b0 = ib * BT;
    const int j0 = jb * JT;

    const uint32_t smem_base = smem_u32(smem_dyn);
    const uint32_t mbar_addr = smem_base + MB_OFF;

    // mma fragment indices
    const int g8 = lane >> 2;                      // 0..7
    const int tg = lane & 3;                       // 0..3

    // ldmatrix per-lane row/koff (same mapping as round 14 — verified)
    const int lrow = (lane & 7) + ((lane >> 3) & 1) * 8;
    const int lkoff = (lane >> 4) * 8;
    const uint32_t hs_frag = smem_base + (uint32_t)(lrow * HST + lkoff) * 2u;
    const uint32_t xs_base = smem_u32(xsh) + (uint32_t)(lrow * XST + lkoff) * 2u;

    // Phase-C mapping
    const int bc = tid >> 5;                       // 0..15
    const int jc = tid & 31;                       // 0..31

    // Local byte offset of this thread's h element within one hs buffer
    const uint32_t elem_off = (uint32_t)(bc * HST + j0 + jc) * 2u;
    // Precompute remote (per-rank) addresses of this element in buffer 0
    uint32_t rh[8];
    #pragma unroll
    for (int r = 0; r < 8; r++) rh[r] = mapa_u32(smem_base + elem_off, r);
    const uint32_t mb_delta = mbar_addr - (smem_base + elem_off);

    // ---- Preload weight fragments into registers ----
    uint32_t bw[48];
    if (wid < 12) {
        const int gate = wid >> 2;
        const int jj0 = (wid & 3) * 8;
        const int col = gate * H + j0 + jj0 + g8;
        #pragma unroll
        for (int kc = 0; kc < 16; kc++) {
            const int kb = kc * 16;
            bw[2 * kc] =
                pack_h2(wr[(size_t)(kb + 2 * tg) * H3 + col],
                        wr[(size_t)(kb + 2 * tg + 1) * H3 + col]);
            bw[2 * kc + 1] =
                pack_h2(wr[(size_t)(kb + 2 * tg + 8) * H3 + col],
                        wr[(size_t)(kb + 2 * tg + 9) * H3 + col]);
        }
    } else {
        #pragma unroll
        for (int ci = 0; ci < 3; ci++) {
            const int cc = (wid - 12) * 3 + ci;
            const int gate = cc >> 2;
            const int jj0 = (cc & 3) * 8;
            const int col = gate * H + j0 + jj0 + g8;
            #pragma unroll
            for (int kc = 0; kc < 8; kc++) {
                const int kb = kc * 16;
                bw[ci * 16 + 2 * kc] =
                    pack_h2(wk[(size_t)(kb + 2 * tg) * H3 + col],
                            wk[(size_t)(kb + 2 * tg + 1) * H3 + col]);
                bw[ci * 16 + 2 * kc + 1] =
                    pack_h2(wk[(size_t)(kb + 2 * tg + 8) * H3 + col],
                            wk[(size_t)(kb + 2 * tg + 9) * H3 + col]);
            }
        }
    }

    // Biases (input + recurrent) for phase C
    const float bzi = bias[j0 + jc];
    const float bri = bias[H + j0 + jc];
    const float bhi = bias[2 * H + j0 + jc];
    const float bzr = bias[H3 + j0 + jc];
    const float brr = bias[H3 + H + j0 + jc];
    const float bhr = bias[H3 + 2 * H + j0 + jc];

    // ---- mbarrier init: 8 CTAs x 512 threads arrive each phase ----
    if (tid == 0) {
        asm volatile("mbarrier.init.shared.b64 [%0], %1;"
                     :: "r"(mbar_addr), "r"(4096u) : "memory");
    }
    __syncthreads();
    CLUSTER_SYNC();   // all mbarriers visible before any remote arrive

    // ---- Prologue: proj warps compute mx_0 into mxs[0] ----
    if (wid >= 12) {
        const int pid = tid - 384;
        #pragma unroll
        for (int i = 0; i < 4; i++) {
            int idx = pid + i * 128;
            int row = idx >> 5, c4 = idx & 31;
            float4 v = *(const float4*)&x[((size_t)(b0 + row) * T + 0) * F + c4 * 4];
            uint2 u;
            u.x = pack_h2(v.x, v.y);
            u.y = pack_h2(v.z, v.w);
            *(uint2*)&xsh[row * XST + c4 * 4] = u;
        }
        asm volatile("bar.sync 2, 128;" ::: "memory");
        uint32_t xa[8][4];
        #pragma unroll
        for (int kc = 0; kc < 8; kc++)
            ldsm_x4(xa[kc][0], xa[kc][1], xa[kc][2], xa[kc][3], xs_base + kc * 32);
        #pragma unroll
        for (int ci = 0; ci < 3; ci++) {
            const int cc = (wid - 12) * 3 + ci;
            const int gate = cc >> 2;
            const int jj0 = (cc & 3) * 8;
            float d[4] = {};
            #pragma unroll
            for (int kc = 0; kc < 8; kc++)
                mma_f16(d, xa[kc][0], xa[kc][1], xa[kc][2], xa[kc][3],
                        bw[ci * 16 + 2 * kc], bw[ci * 16 + 2 * kc + 1]);
            float* mr0 = mxs + g8 * MXS + gate * 32 + jj0 + 2 * tg;
            *(float2*)mr0 = make_float2(d[0], d[1]);
            *(float2*)(mr0 + 8 * MXS) = make_float2(d[2], d[3]);
        }
    }

    float hp = 0.0f;                               // carried own h element

    for (int t = 0; t < T; t++) {
        if (wid >= 12) {
            // ===== PROJ: mx_{t+1} into mxs[(t+1)&1] (one step ahead) =====
            if (t + 1 < T) {
                const int pid = tid - 384;
                #pragma unroll
                for (int i = 0; i < 4; i++) {
                    int idx = pid + i * 128;
                    int row = idx >> 5, c4 = idx & 31;
                    float4 v = *(const float4*)
                        &x[((size_t)(b0 + row) * T + (t + 1)) * F + c4 * 4];
                    uint2 u;
                    u.x = pack_h2(v.x, v.y);
                    u.y = pack_h2(v.z, v.w);
                    *(uint2*)&xsh[row * XST + c4 * 4] = u;
                }
                asm volatile("bar.sync 2, 128;" ::: "memory");
                uint32_t xa[8][4];
                #pragma unroll
                for (int kc = 0; kc < 8; kc++)
                    ldsm_x4(xa[kc][0], xa[kc][1], xa[kc][2], xa[kc][3],
                            xs_base + kc * 32);
                float* mxb = mxs + ((t + 1) & 1) * (BT * MXS);
                #pragma unroll
                for (int ci = 0; ci < 3; ci++) {
                    const int cc = (wid - 12) * 3 + ci;
                    const int gate = cc >> 2;
                    const int jj0 = (cc & 3) * 8;
                    float d[4] = {};
                    #pragma unroll
                    for (int kc = 0; kc < 8; kc++)
                        mma_f16(d, xa[kc][0], xa[kc][1], xa[kc][2], xa[kc][3],
                                bw[ci * 16 + 2 * kc], bw[ci * 16 + 2 * kc + 1]);
                    float* mr0 = mxb + g8 * MXS + gate * 32 + jj0 + 2 * tg;
                    *(float2*)mr0 = make_float2(d[0], d[1]);
                    *(float2*)(mr0 + 8 * MXS) = make_float2(d[2], d[3]);
                }
            }
        } else if (t > 0) {
            // ===== REC (warps 0-11): wait for h(t-1), then mma =====
            mbar_wait_parity_acq_cluster(mbar_addr, (unsigned)((t - 1) & 1));
            const uint32_t hbase = hs_frag + (uint32_t)(((t - 1) & 1) * HSBUF_BYTES);
            float d[4] = {};
            #pragma unroll
            for (int kc = 0; kc < 16; kc++) {
                uint32_t a0, a1, a2, a3;
                ldsm_x4(a0, a1, a2, a3, hbase + kc * 32);
                mma_f16(d, a0, a1, a2, a3, bw[2 * kc], bw[2 * kc + 1]);
            }
            const int gate = wid >> 2;
            const int jj0 = (wid & 3) * 8;
            float* pr0 = pt + g8 * PTS + gate * 32 + jj0 + 2 * tg;
            *(float2*)pr0 = make_float2(d[0], d[1]);
            *(float2*)(pr0 + 8 * PTS) = make_float2(d[2], d[3]);
        }
        __syncthreads();   // barB: pt + mxs[t&1] ready for phase C

        // ===== PHASE C: gates + DSMEM push (all 512 threads) =====
        {
            const float* mrow = mxs + (t & 1) * (BT * MXS) + bc * MXS;
            float xz = mrow[jc] + bzi;
            float xr = mrow[32 + jc] + bri;
            float xh = mrow[64 + jc] + bhi;
            float mz = 0.f, mr = 0.f, mh = 0.f;
            if (t > 0) {
                const float* p = pt + bc * PTS + jc;
                mz = p[0];
                mr = p[32];
                mh = p[64];
            }
            float z = sig_fast(xz + mz + bzr);
            float r = sig_fast(xr + mr + brr);
            float c = tanh_fast(xh + r * (mh + bhr));
            float o = c + z * (hp - c);
            hp = o;

            if (t + 1 < T) {
                const uint16_t oh16 =
                    __half_as_ushort(__float2half_rn(o));
                const uint32_t bufoff = (uint32_t)((t & 1) * HSBUF_BYTES);
                // push h element into all 8 CTAs' hsh[t&1]
                #pragma unroll
                for (int r8 = 0; r8 < 8; r8++)
                    st_cluster_u16(rh[r8] + bufoff, oh16);
                // release-arrive on all 8 CTAs' mbarriers
                #pragma unroll
                for (int r8 = 0; r8 < 8; r8++)
                    mbar_arrive_rel_cluster(rh[r8] + mb_delta);
            }
            // fp32 result store: nothing reads it -> off the critical path
            out[(size_t)t * BH + (size_t)(b0 + bc) * H + j0 + jc] = o;
        }
    }

    // Guard in-flight DSMEM ops before any CTA tears down
    CLUSTER_SYNC();
}

// ---------------------------------------------------------------------------
// Launch
// ---------------------------------------------------------------------------
extern "C" void kernel_launch(void* const* d_in, const int* in_sizes, int n_in,
                              void* d_out, int out_size) {
    (void)in_sizes; (void)n_in; (void)out_size;
    const float* x    = (const float*)d_in[0];   // (B, T, F)
    const float* wk   = (const float*)d_in[1];   // (F, 3H)
    const float* wr   = (const float*)d_in[2];   // (H, 3H)
    const float* bias = (const float*)d_in[3];   // (2, 3H)
    float* out = (float*)d_out;                  // (T, B, H)

    static int attr_set = 0;
    if (!attr_set) {
        cudaFuncSetAttribute(gru_persist,
                             cudaFuncAttributeMaxDynamicSharedMemorySize,
                             SMEM_BYTES);
        attr_set = 1;
    }

    dim3 g2(8, 16);                              // 16 clusters of 8 along x
    gru_persist<<<g2, 512, SMEM_BYTES>>>(x, wk, wr, bias, out);
}

// round 16
// speedup vs baseline: 1.4330x; 1.4330x over previous
#include <cuda_runtime.h>
#include <cuda_fp16.h>
#include <math.h>
#include <stdint.h>

#define B 256
#define T 512
#define F 128
#define H 256
#define H3 768
#define BH (B * H)

// ---------------------------------------------------------------------------
// Helpers
// ---------------------------------------------------------------------------
__device__ __forceinline__ float tanh_fast(float x) {
    float y;
    asm("tanh.approx.f32 %0, %1;" : "=f"(y) : "f"(x));
    return y;
}
__device__ __forceinline__ float sig_fast(float x) {
    return fmaf(0.5f, tanh_fast(0.5f * x), 0.5f);
}
__device__ __forceinline__ uint32_t pack_h2(float lo, float hi) {
    half2 h = __floats2half2_rn(lo, hi);
    return *reinterpret_cast<uint32_t*>(&h);
}
__device__ __forceinline__ uint32_t smem_u32(const void* p) {
    uint32_t a;
    asm("{ .reg .u64 t; cvta.to.shared.u64 t, %1; cvt.u32.u64 %0, t; }"
        : "=r"(a) : "l"(p));
    return a;
}
__device__ __forceinline__ void mma_f16(float* d,
                                        uint32_t a0, uint32_t a1, uint32_t a2, uint32_t a3,
                                        uint32_t b0, uint32_t b1) {
    asm volatile(
        "mma.sync.aligned.m16n8k16.row.col.f32.f16.f16.f32 "
        "{%0,%1,%2,%3}, {%4,%5,%6,%7}, {%8,%9}, {%0,%1,%2,%3};"
        : "+f"(d[0]), "+f"(d[1]), "+f"(d[2]), "+f"(d[3])
        : "r"(a0), "r"(a1), "r"(a2), "r"(a3), "r"(b0), "r"(b1));
}
__device__ __forceinline__ void ldsm_x4(uint32_t& a0, uint32_t& a1,
                                        uint32_t& a2, uint32_t& a3, uint32_t saddr) {
    asm volatile("ldmatrix.sync.aligned.m8n8.x4.shared.b16 {%0,%1,%2,%3}, [%4];"
                 : "=r"(a0), "=r"(a1), "=r"(a2), "=r"(a3) : "r"(saddr));
}
__device__ __forceinline__ uint32_t mapa_u32(uint32_t addr, int rank) {
    uint32_t r;
    asm("mapa.shared::cluster.u32 %0, %1, %2;" : "=r"(r) : "r"(addr), "r"(rank));
    return r;
}
__device__ __forceinline__ void st_cluster_u64(uint32_t addr, unsigned long long v) {
    asm volatile("st.shared::cluster.u64 [%0], %1;" :: "r"(addr), "l"(v) : "memory");
}
__device__ __forceinline__ void mbar_arrive_rel_cluster(uint32_t addr) {
    asm volatile("mbarrier.arrive.release.cluster.shared::cluster.b64 _, [%0];"
                 :: "r"(addr) : "memory");
}
__device__ __forceinline__ void mbar_wait_parity_acq_cluster(uint32_t addr,
                                                             uint32_t parity) {
    asm volatile(
        "{\n\t"
        ".reg .pred p;\n\t"
        "WAITLOOP_%=:\n\t"
        "mbarrier.try_wait.parity.acquire.cluster.shared::cta.b64 p, [%0], %1;\n\t"
        "@!p bra WAITLOOP_%=;\n\t"
        "}"
        :: "r"(addr), "r"(parity) : "memory");
}
#define CLUSTER_SYNC() do { \
    asm volatile("barrier.cluster.arrive.aligned;" ::: "memory"); \
    asm volatile("barrier.cluster.wait.aligned;" ::: "memory"); \
} while (0)

// ---------------------------------------------------------------------------
// Persistent fused GRU kernel — cluster/DSMEM WARP-BULK push version.
// Grid (8 j-tiles, 16 b-groups) = 128 blocks, cluster (8,1,1), 512 thr.
//
// Warps 0-11:  recurrence mh = h(t-1) @ Wr; one n8-chunk each (16 HMMA);
//              Wr frags in 32 regs; A frags via ldmatrix.x4; arrival of
//              h(t-1) signaled by ONE local mbarrier (count 8).
// Warps 12-15: input projection mx_{t+1} (one step ahead), mxs dbl-buf.
// Phase C:     512 threads, 1 element; fp32 gates; STS own fp16 element
//              into local hsh[t&1]; barC.
// Push:        warps 0-6 bulk-copy the local 1KB own tile to ONE peer each
//              (st.shared::cluster.u64, 32B/lane), __syncwarp, lane0 does
//              one mbarrier.arrive.release.cluster. tid224 arrives locally.
//              => 8 arrives/barrier/phase (vs 4096 in round 15).
// ---------------------------------------------------------------------------
#define BT 16
#define JT 32
#define HST 264                     // hs row stride in halves (LDSM-clean)
#define XST 136                     // xs row stride in halves
#define PTS 100                     // mh tile row stride (f32)
#define MXS 100                     // mx tile row stride (f32)

#define HSBUF_HALVES (BT * HST)
#define HSBUF_BYTES (HSBUF_HALVES * 2)     // 8448
#define HS_BYTES (2 * HSBUF_BYTES)         // 16896
#define XS_BYTES (BT * XST * 2)            // 4352
#define PT_BYTES (BT * PTS * 4)            // 6400
#define MX_BYTES (2 * BT * MXS * 4)        // 12800
#define MB_OFF (HS_BYTES + XS_BYTES + PT_BYTES + MX_BYTES)
#define SMEM_BYTES (MB_OFF + 16)

extern __shared__ char smem_dyn[];

__global__ __launch_bounds__(512, 1) __cluster_dims__(8, 1, 1)
void gru_persist(const float* __restrict__ x,
                 const float* __restrict__ wk,
                 const float* __restrict__ wr,
                 const float* __restrict__ bias,
                 float* __restrict__ out) {
    half*  hsh = (half*)(smem_dyn);                         // [2][16][HST]
    half*  xsh = (half*)(smem_dyn + HS_BYTES);              // [16][XST]
    float* pt  = (float*)(smem_dyn + HS_BYTES + XS_BYTES);  // [16][PTS]
    float* mxs = (float*)(smem_dyn + HS_BYTES + XS_BYTES + PT_BYTES); // [2][16][MXS]

    const int tid = (int)threadIdx.x;              // 0..511
    const int wid = tid >> 5;                      // 0..15
    const int lane = tid & 31;
    const int jb = (int)blockIdx.x;                // 0..7 == cluster rank
    const int ib = (int)blockIdx.y;                // 0..15
    const int b0 = ib * BT;
    const int j0 = jb * JT;

    const uint32_t smem_base = smem_u32(smem_dyn);
    const uint32_t mbar_addr = smem_base + MB_OFF;

    // mma fragment indices
    const int g8 = lane >> 2;                      // 0..7
    const int tg = lane & 3;                       // 0..3

    // ldmatrix per-lane row/koff
    const int lrow = (lane & 7) + ((lane >> 3) & 1) * 8;
    const int lkoff = (lane >> 4) * 8;
    const uint32_t hs_frag = smem_base + (uint32_t)(lrow * HST + lkoff) * 2u;
    const uint32_t xs_base = smem_u32(xsh) + (uint32_t)(lrow * XST + lkoff) * 2u;

    // Phase-C mapping
    const int bc = tid >> 5;                       // 0..15
    const int jc = tid & 31;                       // 0..31

    // Push mapping: warps 0-6 -> peer (jb+1+wid)&7; 32B per lane
    const int ppeer = (jb + 1 + wid) & 7;
    const int prow = lane >> 1;                    // 0..15
    const int pseg = (lane & 1) * 16;              // halves offset 0 or 16
    const uint32_t poff = (uint32_t)(prow * HST + j0 + pseg) * 2u;  // bytes in buf0
    const uint32_t psrc = smem_base + poff;        // local source
    const uint32_t pdst = mapa_u32(psrc, ppeer);   // remote dest (same offset)
    const uint32_t pmb  = mapa_u32(mbar_addr, ppeer);

    // ---- Preload weight fragments into registers ----
    uint32_t bw[48];
    if (wid < 12) {
        const int gate = wid >> 2;
        const int jj0 = (wid & 3) * 8;
        const int col = gate * H + j0 + jj0 + g8;
        #pragma unroll
        for (int kc = 0; kc < 16; kc++) {
            const int kb = kc * 16;
            bw[2 * kc] =
                pack_h2(wr[(size_t)(kb + 2 * tg) * H3 + col],
                        wr[(size_t)(kb + 2 * tg + 1) * H3 + col]);
            bw[2 * kc + 1] =
                pack_h2(wr[(size_t)(kb + 2 * tg + 8) * H3 + col],
                        wr[(size_t)(kb + 2 * tg + 9) * H3 + col]);
        }
    } else {
        #pragma unroll
        for (int ci = 0; ci < 3; ci++) {
            const int cc = (wid - 12) * 3 + ci;
            const int gate = cc >> 2;
            const int jj0 = (cc & 3) * 8;
            const int col = gate * H + j0 + jj0 + g8;
            #pragma unroll
            for (int kc = 0; kc < 8; kc++) {
                const int kb = kc * 16;
                bw[ci * 16 + 2 * kc] =
                    pack_h2(wk[(size_t)(kb + 2 * tg) * H3 + col],
                            wk[(size_t)(kb + 2 * tg + 1) * H3 + col]);
                bw[ci * 16 + 2 * kc + 1] =
                    pack_h2(wk[(size_t)(kb + 2 * tg + 8) * H3 + col],
                            wk[(size_t)(kb + 2 * tg + 9) * H3 + col]);
            }
        }
    }

    // Biases (input + recurrent) for phase C
    const float bzi = bias[j0 + jc];
    const float bri = bias[H + j0 + jc];
    const float bhi = bias[2 * H + j0 + jc];
    const float bzr = bias[H3 + j0 + jc];
    const float brr = bias[H3 + H + j0 + jc];
    const float bhr = bias[H3 + 2 * H + j0 + jc];

    // ---- mbarrier init: 8 arrives per phase (7 remote + 1 local) ----
    if (tid == 0) {
        asm volatile("mbarrier.init.shared.b64 [%0], %1;"
                     :: "r"(mbar_addr), "r"(8u) : "memory");
    }
    // zero h buffers (hygiene)
    for (int i = tid; i < 2 * HSBUF_HALVES; i += 512) hsh[i] = __ushort_as_half(0);
    __syncthreads();
    CLUSTER_SYNC();   // all mbarriers visible before any remote arrive

    // ---- Prologue: proj warps compute mx_0 into mxs[0] ----
    if (wid >= 12) {
        const int pid = tid - 384;
        #pragma unroll
        for (int i = 0; i < 4; i++) {
            int idx = pid + i * 128;
            int row = idx >> 5, c4 = idx & 31;
            float4 v = *(const float4*)&x[((size_t)(b0 + row) * T + 0) * F + c4 * 4];
            uint2 u;
            u.x = pack_h2(v.x, v.y);
            u.y = pack_h2(v.z, v.w);
            *(uint2*)&xsh[row * XST + c4 * 4] = u;
        }
        asm volatile("bar.sync 2, 128;" ::: "memory");
        uint32_t xa[8][4];
        #pragma unroll
        for (int kc = 0; kc < 8; kc++)
            ldsm_x4(xa[kc][0], xa[kc][1], xa[kc][2], xa[kc][3], xs_base + kc * 32);
        #pragma unroll
        for (int ci = 0; ci < 3; ci++) {
            const int cc = (wid - 12) * 3 + ci;
            const int gate = cc >> 2;
            const int jj0 = (cc & 3) * 8;
            float d[4] = {};
            #pragma unroll
            for (int kc = 0; kc < 8; kc++)
                mma_f16(d, xa[kc][0], xa[kc][1], xa[kc][2], xa[kc][3],
                        bw[ci * 16 + 2 * kc], bw[ci * 16 + 2 * kc + 1]);
            float* mr0 = mxs + g8 * MXS + gate * 32 + jj0 + 2 * tg;
            *(float2*)mr0 = make_float2(d[0], d[1]);
            *(float2*)(mr0 + 8 * MXS) = make_float2(d[2], d[3]);
        }
    }

    float hp = 0.0f;                               // carried own h element

    for (int t = 0; t < T; t++) {
        if (wid >= 12) {
            // ===== PROJ: mx_{t+1} into mxs[(t+1)&1] =====
            if (t + 1 < T) {
                const int pid = tid - 384;
                #pragma unroll
                for (int i = 0; i < 4; i++) {
                    int idx = pid + i * 128;
                    int row = idx >> 5, c4 = idx & 31;
                    float4 v = *(const float4*)
                        &x[((size_t)(b0 + row) * T + (t + 1)) * F + c4 * 4];
                    uint2 u;
                    u.x = pack_h2(v.x, v.y);
                    u.y = pack_h2(v.z, v.w);
                    *(uint2*)&xsh[row * XST + c4 * 4] = u;
                }
                asm volatile("bar.sync 2, 128;" ::: "memory");
                uint32_t xa[8][4];
                #pragma unroll
                for (int kc = 0; kc < 8; kc++)
                    ldsm_x4(xa[kc][0], xa[kc][1], xa[kc][2], xa[kc][3],
                            xs_base + kc * 32);
                float* mxb = mxs + ((t + 1) & 1) * (BT * MXS);
                #pragma unroll
                for (int ci = 0; ci < 3; ci++) {
                    const int cc = (wid - 12) * 3 + ci;
                    const int gate = cc >> 2;
                    const int jj0 = (cc & 3) * 8;
                    float d[4] = {};
                    #pragma unroll
                    for (int kc = 0; kc < 8; kc++)
                        mma_f16(d, xa[kc][0], xa[kc][1], xa[kc][2], xa[kc][3],
                                bw[ci * 16 + 2 * kc], bw[ci * 16 + 2 * kc + 1]);
                    float* mr0 = mxb + g8 * MXS + gate * 32 + jj0 + 2 * tg;
                    *(float2*)mr0 = make_float2(d[0], d[1]);
                    *(float2*)(mr0 + 8 * MXS) = make_float2(d[2], d[3]);
                }
            }
        } else if (t > 0) {
            // ===== REC (warps 0-11): wait for h(t-1), then mma =====
            mbar_wait_parity_acq_cluster(mbar_addr, (unsigned)((t - 1) & 1));
            const uint32_t hbase = hs_frag + (uint32_t)(((t - 1) & 1) * HSBUF_BYTES);
            float d[4] = {};
            #pragma unroll
            for (int kc = 0; kc < 16; kc++) {
                uint32_t a0, a1, a2, a3;
                ldsm_x4(a0, a1, a2, a3, hbase + kc * 32);
                mma_f16(d, a0, a1, a2, a3, bw[2 * kc], bw[2 * kc + 1]);
            }
            const int gate = wid >> 2;
            const int jj0 = (wid & 3) * 8;
            float* pr0 = pt + g8 * PTS + gate * 32 + jj0 + 2 * tg;
            *(float2*)pr0 = make_float2(d[0], d[1]);
            *(float2*)(pr0 + 8 * PTS) = make_float2(d[2], d[3]);
        }
        __syncthreads();   // barB: pt + mxs[t&1] ready

        // ===== PHASE C: gates (all 512 threads) =====
        float o;
        {
            const float* mrow = mxs + (t & 1) * (BT * MXS) + bc * MXS;
            float xz = mrow[jc] + bzi;
            float xr = mrow[32 + jc] + bri;
            float xh = mrow[64 + jc] + bhi;
            float mz = 0.f, mr = 0.f, mh = 0.f;
            if (t > 0) {
                const float* p = pt + bc * PTS + jc;
                mz = p[0];
                mr = p[32];
                mh = p[64];
            }
            float z = sig_fast(xz + mz + bzr);
            float r = sig_fast(xr + mr + brr);
            float c = tanh_fast(xh + r * (mh + bhr));
            o = c + z * (hp - c);
            hp = o;
            // own fp16 tile into local hsh[t&1]
            hsh[(t & 1) * HSBUF_HALVES + bc * HST + j0 + jc] = __float2half_rn(o);
        }
        __syncthreads();   // barC: own tile complete locally

        // ===== PUSH: warps 0-6 bulk-copy own tile to one peer each =====
        if (t + 1 < T) {
            if (wid < 7) {
                const uint32_t bufoff = (uint32_t)((t & 1) * HSBUF_BYTES);
                ulonglong2 v0 = *(const ulonglong2*)(smem_dyn + (psrc - smem_base) + bufoff);
                ulonglong2 v1 = *(const ulonglong2*)(smem_dyn + (psrc - smem_base) + bufoff + 16);
                st_cluster_u64(pdst + bufoff +  0, v0.x);
                st_cluster_u64(pdst + bufoff +  8, v0.y);
                st_cluster_u64(pdst + bufoff + 16, v1.x);
                st_cluster_u64(pdst + bufoff + 24, v1.y);
                __syncwarp();
                if (lane == 0) mbar_arrive_rel_cluster(pmb);
            }
            if (tid == 224) {   // local arrive (own tile ordered by barC)
                mbar_arrive_rel_cluster(mbar_addr);
            }
        }
        // fp32 result store: nothing reads it -> off the critical path
        out[(size_t)t * BH + (size_t)(b0 + bc) * H + j0 + jc] = o;
    }

    CLUSTER_SYNC();   // guard in-flight DSMEM ops before teardown
}

// ---------------------------------------------------------------------------
// Launch
// ---------------------------------------------------------------------------
extern "C" void kernel_launch(void* const* d_in, const int* in_sizes, int n_in,
                              void* d_out, int out_size) {
    (void)in_sizes; (void)n_in; (void)out_size;
    const float* x    = (const float*)d_in[0];   // (B, T, F)
    const float* wk   = (const float*)d_in[1];   // (F, 3H)
    const float* wr   = (const float*)d_in[2];   // (H, 3H)
    const float* bias = (const float*)d_in[3];   // (2, 3H)
    float* out = (float*)d_out;                  // (T, B, H)

    static int attr_set = 0;
    if (!attr_set) {
        cudaFuncSetAttribute(gru_persist,
                             cudaFuncAttributeMaxDynamicSharedMemorySize,
                             SMEM_BYTES);
        attr_set = 1;
    }

    dim3 g2(8, 16);                              // 16 clusters of 8 along x
    gru_persist<<<g2, 512, SMEM_BYTES>>>(x, wk, wr, bias, out);
}